// round 14
// baseline (speedup 1.0000x reference)
#include <cuda_runtime.h>
#include <math_constants.h>

#define N_BINS 15
#define RPW 8          // rows per warp per iter (one row per 4-lane segment)

// Global scratch (no allocation allowed). Zeroed at module load; the fused
// finalizer re-zeroes after each use, so every graph replay starts from zero.
__device__ float    g_cnt[N_BINS];
__device__ float    g_conf[N_BINS];
__device__ float    g_acc[N_BINS];
__device__ unsigned g_done;

__device__ __forceinline__ float ex2f(float x) {
    float r;
    asm volatile("ex2.approx.f32 %0, %1;" : "=f"(r) : "f"(x));
    return r;
}

// Global float4 load with L2::256B prefetch-size hint: each L2 miss fetches a
// 256B-aligned window. Rows are 512B-aligned and fully consumed -> no waste,
// fewer/larger DRAM bursts.
__device__ __forceinline__ float4 ldg256(const float4* p) {
    float4 v;
    asm volatile("ld.global.L2::256B.v4.f32 {%0,%1,%2,%3}, [%4];"
                 : "=f"(v.x), "=f"(v.y), "=f"(v.z), "=f"(v.w)
                 : "l"(p));
    return v;
}

#define LOG2E 1.4426950408889634f

// Extract column `lab` (0..127) of the row held by this 4-lane segment.
// Lane sub owns float4 indices {sub, sub+4, ..., sub+28} (stride 4).
// Returns the value on the owning lane (garbage elsewhere) + ownership flag.
// Pure SEL chain — no dependent memory load.
__device__ __forceinline__ float extract_col4(const float4 v[RPW], int lab,
                                              int sub, bool& owner)
{
    int f4 = lab >> 2;                 // float4 index 0..31
    owner  = ((f4 & 3) == sub);        // owning lane within 4-lane segment
    int i  = f4 >> 2;                  // which of my 8 float4s (0..7)
    int c  = lab & 3;                  // component
    float e[RPW];
    #pragma unroll
    for (int k = 0; k < RPW; k++) {
        float lo = (c & 1) ? v[k].y : v[k].x;
        float hi = (c & 1) ? v[k].w : v[k].z;
        e[k] = (c & 2) ? hi : lo;
    }
    float a01 = (i & 1) ? e[1] : e[0];
    float a23 = (i & 1) ? e[3] : e[2];
    float a45 = (i & 1) ? e[5] : e[4];
    float a67 = (i & 1) ? e[7] : e[6];
    float b0  = (i & 2) ? a23 : a01;
    float b1  = (i & 2) ? a67 : a45;
    return (i & 4) ? b1 : b0;
}

// 4 lanes per row, lane covers 32 floats (8 float4, stride-4).
// A warp processes 8 consecutive rows per iteration (4 KB, front-batched).
// No atomics and no dependent loads in the hot loop. Register histogram:
// lane b (<15) owns bin b.
__global__ void __launch_bounds__(256, 4) mce_main_kernel(
    const float4* __restrict__ logits4,   // [nrows * 32] float4
    const int*    __restrict__ labels,    // [nrows]
    float*        __restrict__ out,
    int nrows)
{
    __shared__ float s_cnt[N_BINS];
    __shared__ float s_conf[N_BINS];
    __shared__ float s_acc[N_BINS];
    __shared__ bool  s_last;

    int tid = threadIdx.x;
    if (tid < N_BINS) {
        s_cnt[tid]  = 0.0f;
        s_conf[tid] = 0.0f;
        s_acc[tid]  = 0.0f;
    }
    __syncthreads();

    int lane   = tid & 31;
    int seg    = lane >> 2;                // row within group (0..7)
    int sub    = lane & 3;                 // lane within 4-lane segment
    int warp   = (blockIdx.x * blockDim.x + tid) >> 5;
    int nwarps = (gridDim.x * blockDim.x) >> 5;

    float r_cnt = 0.0f, r_conf = 0.0f, r_acc = 0.0f;

    for (int base = warp * RPW; base < nrows; base += nwarps * RPW) {
        int row  = base + seg;
        int rowc = (row < nrows) ? row : (nrows - 1);   // clamp tail

        // ---- independent front batch: 8 LDG.128 + 1 label LDG per lane ----
        int lab = labels[rowc];            // broadcast within segment
        float4 v[RPW];
        const float4* rp = logits4 + (size_t)rowc * 32 + sub;
        #pragma unroll
        for (int i = 0; i < RPW; i++) v[i] = ldg256(rp + 4 * i);

        // ---- per-lane max over 32 values, tree ----
        float pm[RPW];
        #pragma unroll
        for (int i = 0; i < RPW; i++)
            pm[i] = fmaxf(fmaxf(v[i].x, v[i].y), fmaxf(v[i].z, v[i].w));
        float m = fmaxf(fmaxf(fmaxf(pm[0], pm[1]), fmaxf(pm[2], pm[3])),
                        fmaxf(fmaxf(pm[4], pm[5]), fmaxf(pm[6], pm[7])));
        // segment butterfly: 2 levels, all 8 rows reduced per instruction
        m = fmaxf(m, __shfl_xor_sync(0xffffffffu, m, 1));
        m = fmaxf(m, __shfl_xor_sync(0xffffffffu, m, 2));

        // ---- sum of exp(x - m) = ex2(x*log2e - m*log2e) ----
        float mL = m * LOG2E;
        float ps[RPW];
        #pragma unroll
        for (int i = 0; i < RPW; i++) {
            float e0 = ex2f(fmaf(v[i].x, LOG2E, -mL));
            float e1 = ex2f(fmaf(v[i].y, LOG2E, -mL));
            float e2 = ex2f(fmaf(v[i].z, LOG2E, -mL));
            float e3 = ex2f(fmaf(v[i].w, LOG2E, -mL));
            ps[i] = (e0 + e1) + (e2 + e3);
        }
        float s = ((ps[0] + ps[1]) + (ps[2] + ps[3]))
                + ((ps[4] + ps[5]) + (ps[6] + ps[7]));
        s += __shfl_xor_sync(0xffffffffu, s, 1);
        s += __shfl_xor_sync(0xffffffffu, s, 2);

        float conf = __fdividef(1.0f, s);      // = exp(max)/sum exp

        // ---- accuracy: label column extracted from registers (no load) ----
        bool own;
        float lv = extract_col4(v, lab, sub, own);
        unsigned b = __ballot_sync(0xffffffffu, own && (lv == m));

        int nr = min(RPW, nrows - base);
        #pragma unroll
        for (int r = 0; r < RPW; r++) {
            float cf = __shfl_sync(0xffffffffu, conf, r * 4);
            unsigned abit = (b >> (4 * r)) & 0xfu;
            // bin i covers (i/15, (i+1)/15]; conf >= 1/128 -> bin >= 0
            int bin = min(__float2int_ru(cf * (float)N_BINS) - 1, N_BINS - 1);
            if (bin == lane && r < nr) {
                r_cnt  += 1.0f;
                r_conf += cf;
                r_acc  += (abit != 0u) ? 1.0f : 0.0f;
            }
        }
    }

    // ---- flush: registers -> shared -> global (once per block) ----
    if (lane < N_BINS && r_cnt != 0.0f) {
        atomicAdd(&s_cnt[lane],  r_cnt);
        atomicAdd(&s_conf[lane], r_conf);
        atomicAdd(&s_acc[lane],  r_acc);
    }
    __syncthreads();
    if (tid < N_BINS) {
        float c = s_cnt[tid];
        if (c != 0.0f) {
            atomicAdd(&g_cnt[tid],  c);
            atomicAdd(&g_conf[tid], s_conf[tid]);
            atomicAdd(&g_acc[tid],  s_acc[tid]);
        }
    }
    __threadfence();
    __syncthreads();

    // ---- last block finalizes (fused; no second launch) ----
    if (tid == 0)
        s_last = (atomicAdd(&g_done, 1u) == gridDim.x - 1u);
    __syncthreads();
    if (s_last && tid == 0) {
        volatile float* vc = g_cnt;
        volatile float* vp = g_conf;
        volatile float* va = g_acc;
        float mce = -CUDART_INF_F;
        #pragma unroll
        for (int i = 0; i < N_BINS; i++) {
            float c    = vc[i];
            float prob = 0.0f, accu = 0.0f;
            if (c > 0.0f) {
                prob = vp[i] / c;
                accu = va[i] / c;
                float gap = fabsf(prob - accu);
                if (gap > mce) mce = gap;
            }
            out[1 + i]          = prob;
            out[1 + N_BINS + i] = accu;
            vc[i] = 0.0f; vp[i] = 0.0f; va[i] = 0.0f;   // reset for next replay
        }
        out[0] = mce;
        g_done = 0u;
    }
}

extern "C" void kernel_launch(void* const* d_in, const int* in_sizes, int n_in,
                              void* d_out, int out_size) {
    const float4* logits4 = (const float4*)d_in[0];
    const int*    labels  = (const int*)d_in[1];
    int nrows = in_sizes[1];               // labels element count == N rows

    // 3 CTAs/SM x 148 SMs = 444 blocks (proven best occupancy point)
    mce_main_kernel<<<444, 256>>>(logits4, labels, (float*)d_out, nrows);
}

// round 15
// speedup vs baseline: 1.0130x; 1.0130x over previous
#include <cuda_runtime.h>
#include <math_constants.h>

#define N_BINS 15
#define RPW 8          // rows per warp per iter (one row per 4-lane segment)

// Global scratch (no allocation allowed). Zeroed at module load; the fused
// finalizer re-zeroes after each use, so every graph replay starts from zero.
__device__ float    g_cnt[N_BINS];
__device__ float    g_conf[N_BINS];
__device__ float    g_acc[N_BINS];
__device__ unsigned g_done;

__device__ __forceinline__ float ex2f(float x) {
    float r;
    asm volatile("ex2.approx.f32 %0, %1;" : "=f"(r) : "f"(x));
    return r;
}

#define LOG2E 1.4426950408889634f

// Extract column `lab` (0..127) of the row held by this 4-lane segment.
// Lane sub owns float4 indices {sub, sub+4, ..., sub+28} (stride 4).
// Returns the value on the owning lane (garbage elsewhere) + ownership flag.
// Pure SEL chain — no dependent memory load.
__device__ __forceinline__ float extract_col4(const float4 v[RPW], int lab,
                                              int sub, bool& owner)
{
    int f4 = lab >> 2;                 // float4 index 0..31
    owner  = ((f4 & 3) == sub);        // owning lane within 4-lane segment
    int i  = f4 >> 2;                  // which of my 8 float4s (0..7)
    int c  = lab & 3;                  // component
    float e[RPW];
    #pragma unroll
    for (int k = 0; k < RPW; k++) {
        float lo = (c & 1) ? v[k].y : v[k].x;
        float hi = (c & 1) ? v[k].w : v[k].z;
        e[k] = (c & 2) ? hi : lo;
    }
    float a01 = (i & 1) ? e[1] : e[0];
    float a23 = (i & 1) ? e[3] : e[2];
    float a45 = (i & 1) ? e[5] : e[4];
    float a67 = (i & 1) ? e[7] : e[6];
    float b0  = (i & 2) ? a23 : a01;
    float b1  = (i & 2) ? a67 : a45;
    return (i & 4) ? b1 : b0;
}

// 4 lanes per row, lane covers 32 floats (8 float4, stride-4).
// A warp processes 8 consecutive rows per iteration (4 KB, front-batched).
// No atomics and no dependent loads in the hot loop. Register histogram:
// lane b (<15) owns bin b.
__global__ void __launch_bounds__(256, 4) mce_main_kernel(
    const float4* __restrict__ logits4,   // [nrows * 32] float4
    const int*    __restrict__ labels,    // [nrows]
    float*        __restrict__ out,
    int nrows)
{
    __shared__ float s_cnt[N_BINS];
    __shared__ float s_conf[N_BINS];
    __shared__ float s_acc[N_BINS];
    __shared__ bool  s_last;

    int tid = threadIdx.x;
    if (tid < N_BINS) {
        s_cnt[tid]  = 0.0f;
        s_conf[tid] = 0.0f;
        s_acc[tid]  = 0.0f;
    }
    __syncthreads();

    int lane   = tid & 31;
    int seg    = lane >> 2;                // row within group (0..7)
    int sub    = lane & 3;                 // lane within 4-lane segment
    int warp   = (blockIdx.x * blockDim.x + tid) >> 5;
    int nwarps = (gridDim.x * blockDim.x) >> 5;

    float r_cnt = 0.0f, r_conf = 0.0f, r_acc = 0.0f;

    for (int base = warp * RPW; base < nrows; base += nwarps * RPW) {
        int row  = base + seg;
        int rowc = (row < nrows) ? row : (nrows - 1);   // clamp tail

        // ---- independent front batch: 8 LDG.128 + 1 label LDG per lane ----
        int lab = labels[rowc];            // broadcast within segment
        float4 v[RPW];
        const float4* rp = logits4 + (size_t)rowc * 32 + sub;
        #pragma unroll
        for (int i = 0; i < RPW; i++) v[i] = __ldcs(rp + 4 * i);

        // ---- per-lane max over 32 values, tree ----
        float pm[RPW];
        #pragma unroll
        for (int i = 0; i < RPW; i++)
            pm[i] = fmaxf(fmaxf(v[i].x, v[i].y), fmaxf(v[i].z, v[i].w));
        float m = fmaxf(fmaxf(fmaxf(pm[0], pm[1]), fmaxf(pm[2], pm[3])),
                        fmaxf(fmaxf(pm[4], pm[5]), fmaxf(pm[6], pm[7])));
        // segment butterfly: 2 levels, all 8 rows reduced per instruction
        m = fmaxf(m, __shfl_xor_sync(0xffffffffu, m, 1));
        m = fmaxf(m, __shfl_xor_sync(0xffffffffu, m, 2));

        // ---- sum of exp(x - m) = ex2(x*log2e - m*log2e) ----
        float mL = m * LOG2E;
        float ps[RPW];
        #pragma unroll
        for (int i = 0; i < RPW; i++) {
            float e0 = ex2f(fmaf(v[i].x, LOG2E, -mL));
            float e1 = ex2f(fmaf(v[i].y, LOG2E, -mL));
            float e2 = ex2f(fmaf(v[i].z, LOG2E, -mL));
            float e3 = ex2f(fmaf(v[i].w, LOG2E, -mL));
            ps[i] = (e0 + e1) + (e2 + e3);
        }
        float s = ((ps[0] + ps[1]) + (ps[2] + ps[3]))
                + ((ps[4] + ps[5]) + (ps[6] + ps[7]));
        s += __shfl_xor_sync(0xffffffffu, s, 1);
        s += __shfl_xor_sync(0xffffffffu, s, 2);

        float conf = __fdividef(1.0f, s);      // = exp(max)/sum exp

        // ---- accuracy: label column extracted from registers (no load) ----
        bool own;
        float lv = extract_col4(v, lab, sub, own);
        unsigned b = __ballot_sync(0xffffffffu, own && (lv == m));

        int nr = min(RPW, nrows - base);
        #pragma unroll
        for (int r = 0; r < RPW; r++) {
            float cf = __shfl_sync(0xffffffffu, conf, r * 4);
            unsigned abit = (b >> (4 * r)) & 0xfu;
            // bin i covers (i/15, (i+1)/15]; conf >= 1/128 -> bin >= 0
            int bin = min(__float2int_ru(cf * (float)N_BINS) - 1, N_BINS - 1);
            if (bin == lane && r < nr) {
                r_cnt  += 1.0f;
                r_conf += cf;
                r_acc  += (abit != 0u) ? 1.0f : 0.0f;
            }
        }
    }

    // ---- flush: registers -> shared -> global (once per block) ----
    if (lane < N_BINS && r_cnt != 0.0f) {
        atomicAdd(&s_cnt[lane],  r_cnt);
        atomicAdd(&s_conf[lane], r_conf);
        atomicAdd(&s_acc[lane],  r_acc);
    }
    __syncthreads();
    if (tid < N_BINS) {
        float c = s_cnt[tid];
        if (c != 0.0f) {
            atomicAdd(&g_cnt[tid],  c);
            atomicAdd(&g_conf[tid], s_conf[tid]);
            atomicAdd(&g_acc[tid],  s_acc[tid]);
        }
    }
    __threadfence();
    __syncthreads();

    // ---- last block finalizes (fused; no second launch) ----
    if (tid == 0)
        s_last = (atomicAdd(&g_done, 1u) == gridDim.x - 1u);
    __syncthreads();
    if (s_last && tid == 0) {
        volatile float* vc = g_cnt;
        volatile float* vp = g_conf;
        volatile float* va = g_acc;
        float mce = -CUDART_INF_F;
        #pragma unroll
        for (int i = 0; i < N_BINS; i++) {
            float c    = vc[i];
            float prob = 0.0f, accu = 0.0f;
            if (c > 0.0f) {
                prob = vp[i] / c;
                accu = va[i] / c;
                float gap = fabsf(prob - accu);
                if (gap > mce) mce = gap;
            }
            out[1 + i]          = prob;
            out[1 + N_BINS + i] = accu;
            vc[i] = 0.0f; vp[i] = 0.0f; va[i] = 0.0f;   // reset for next replay
        }
        out[0] = mce;
        g_done = 0u;
    }
}

extern "C" void kernel_launch(void* const* d_in, const int* in_sizes, int n_in,
                              void* d_out, int out_size) {
    const float4* logits4 = (const float4*)d_in[0];
    const int*    labels  = (const int*)d_in[1];
    int nrows = in_sizes[1];               // labels element count == N rows

    // 3 CTAs/SM x 148 SMs = 444 blocks (proven best occupancy point)
    mce_main_kernel<<<444, 256>>>(logits4, labels, (float*)d_out, nrows);
}

// round 16
// speedup vs baseline: 1.0181x; 1.0050x over previous
#include <cuda_runtime.h>
#include <math_constants.h>

#define N_BINS 15
#define RPW 8          // rows per warp per iter (one row per 4-lane segment)

// Global scratch (no allocation allowed). Zeroed at module load; the fused
// finalizer re-zeroes after each use, so every graph replay starts from zero.
__device__ float    g_cnt[N_BINS];
__device__ float    g_conf[N_BINS];
__device__ float    g_acc[N_BINS];
__device__ unsigned g_done;

__device__ __forceinline__ float ex2f(float x) {
    float r;
    asm volatile("ex2.approx.f32 %0, %1;" : "=f"(r) : "f"(x));
    return r;
}

#define LOG2E 1.4426950408889634f

// Extract column `lab` (0..127) of the row held by this 4-lane segment.
// Lane sub owns float4 indices {sub, sub+4, ..., sub+28} (stride 4).
// Returns the value on the owning lane (garbage elsewhere) + ownership flag.
// Pure SEL chain — no dependent memory load.
__device__ __forceinline__ float extract_col4(const float4 v[RPW], int lab,
                                              int sub, bool& owner)
{
    int f4 = lab >> 2;                 // float4 index 0..31
    owner  = ((f4 & 3) == sub);        // owning lane within 4-lane segment
    int i  = f4 >> 2;                  // which of my 8 float4s (0..7)
    int c  = lab & 3;                  // component
    float e[RPW];
    #pragma unroll
    for (int k = 0; k < RPW; k++) {
        float lo = (c & 1) ? v[k].y : v[k].x;
        float hi = (c & 1) ? v[k].w : v[k].z;
        e[k] = (c & 2) ? hi : lo;
    }
    float a01 = (i & 1) ? e[1] : e[0];
    float a23 = (i & 1) ? e[3] : e[2];
    float a45 = (i & 1) ? e[5] : e[4];
    float a67 = (i & 1) ? e[7] : e[6];
    float b0  = (i & 2) ? a23 : a01;
    float b1  = (i & 2) ? a67 : a45;
    return (i & 4) ? b1 : b0;
}

// 4 lanes per row, lane covers 32 floats (8 float4, stride-4).
// A warp processes 8 consecutive rows per iteration (4 KB, front-batched).
// No atomics and no dependent loads in the hot loop. Register histogram:
// lane b (<15) owns bin b.
__global__ void __launch_bounds__(256, 4) mce_main_kernel(
    const float4* __restrict__ logits4,   // [nrows * 32] float4
    const int*    __restrict__ labels,    // [nrows]
    float*        __restrict__ out,
    int nrows)
{
    __shared__ float s_cnt[N_BINS];
    __shared__ float s_conf[N_BINS];
    __shared__ float s_acc[N_BINS];
    __shared__ bool  s_last;

    int tid = threadIdx.x;
    if (tid < N_BINS) {
        s_cnt[tid]  = 0.0f;
        s_conf[tid] = 0.0f;
        s_acc[tid]  = 0.0f;
    }
    __syncthreads();

    int lane   = tid & 31;
    int seg    = lane >> 2;                // row within group (0..7)
    int sub    = lane & 3;                 // lane within 4-lane segment
    int warp   = (blockIdx.x * blockDim.x + tid) >> 5;
    int nwarps = (gridDim.x * blockDim.x) >> 5;

    float r_cnt = 0.0f, r_conf = 0.0f, r_acc = 0.0f;

    for (int base = warp * RPW; base < nrows; base += nwarps * RPW) {
        int row  = base + seg;
        int rowc = (row < nrows) ? row : (nrows - 1);   // clamp tail

        // ---- independent front batch: 8 LDG.128 + 1 label LDG per lane ----
        int lab = labels[rowc];            // broadcast within segment
        float4 v[RPW];
        const float4* rp = logits4 + (size_t)rowc * 32 + sub;
        #pragma unroll
        for (int i = 0; i < RPW; i++) v[i] = __ldcs(rp + 4 * i);

        // ---- per-lane max over 32 values, tree ----
        float pm[RPW];
        #pragma unroll
        for (int i = 0; i < RPW; i++)
            pm[i] = fmaxf(fmaxf(v[i].x, v[i].y), fmaxf(v[i].z, v[i].w));
        float m = fmaxf(fmaxf(fmaxf(pm[0], pm[1]), fmaxf(pm[2], pm[3])),
                        fmaxf(fmaxf(pm[4], pm[5]), fmaxf(pm[6], pm[7])));
        // segment butterfly: 2 levels, all 8 rows reduced per instruction
        m = fmaxf(m, __shfl_xor_sync(0xffffffffu, m, 1));
        m = fmaxf(m, __shfl_xor_sync(0xffffffffu, m, 2));

        // ---- sum of exp(x - m) = ex2(x*log2e - m*log2e) ----
        float mL = m * LOG2E;
        float ps[RPW];
        #pragma unroll
        for (int i = 0; i < RPW; i++) {
            float e0 = ex2f(fmaf(v[i].x, LOG2E, -mL));
            float e1 = ex2f(fmaf(v[i].y, LOG2E, -mL));
            float e2 = ex2f(fmaf(v[i].z, LOG2E, -mL));
            float e3 = ex2f(fmaf(v[i].w, LOG2E, -mL));
            ps[i] = (e0 + e1) + (e2 + e3);
        }
        float s = ((ps[0] + ps[1]) + (ps[2] + ps[3]))
                + ((ps[4] + ps[5]) + (ps[6] + ps[7]));
        s += __shfl_xor_sync(0xffffffffu, s, 1);
        s += __shfl_xor_sync(0xffffffffu, s, 2);

        float conf = __fdividef(1.0f, s);      // = exp(max)/sum exp

        // ---- accuracy: label column extracted from registers (no load) ----
        bool own;
        float lv = extract_col4(v, lab, sub, own);
        unsigned b = __ballot_sync(0xffffffffu, own && (lv == m));

        int nr = min(RPW, nrows - base);
        #pragma unroll
        for (int r = 0; r < RPW; r++) {
            float cf = __shfl_sync(0xffffffffu, conf, r * 4);
            unsigned abit = (b >> (4 * r)) & 0xfu;
            // bin i covers (i/15, (i+1)/15]; conf >= 1/128 -> bin >= 0
            int bin = min(__float2int_ru(cf * (float)N_BINS) - 1, N_BINS - 1);
            if (bin == lane && r < nr) {
                r_cnt  += 1.0f;
                r_conf += cf;
                r_acc  += (abit != 0u) ? 1.0f : 0.0f;
            }
        }
    }

    // ---- flush: registers -> shared -> global (once per block) ----
    if (lane < N_BINS && r_cnt != 0.0f) {
        atomicAdd(&s_cnt[lane],  r_cnt);
        atomicAdd(&s_conf[lane], r_conf);
        atomicAdd(&s_acc[lane],  r_acc);
    }
    __syncthreads();
    if (tid < N_BINS) {
        float c = s_cnt[tid];
        if (c != 0.0f) {
            atomicAdd(&g_cnt[tid],  c);
            atomicAdd(&g_conf[tid], s_conf[tid]);
            atomicAdd(&g_acc[tid],  s_acc[tid]);
        }
    }
    __threadfence();
    __syncthreads();

    // ---- last block finalizes (fused; no second launch) ----
    if (tid == 0)
        s_last = (atomicAdd(&g_done, 1u) == gridDim.x - 1u);
    __syncthreads();
    if (s_last && tid == 0) {
        volatile float* vc = g_cnt;
        volatile float* vp = g_conf;
        volatile float* va = g_acc;
        float mce = -CUDART_INF_F;
        #pragma unroll
        for (int i = 0; i < N_BINS; i++) {
            float c    = vc[i];
            float prob = 0.0f, accu = 0.0f;
            if (c > 0.0f) {
                prob = vp[i] / c;
                accu = va[i] / c;
                float gap = fabsf(prob - accu);
                if (gap > mce) mce = gap;
            }
            out[1 + i]          = prob;
            out[1 + N_BINS + i] = accu;
            vc[i] = 0.0f; vp[i] = 0.0f; va[i] = 0.0f;   // reset for next replay
        }
        out[0] = mce;
        g_done = 0u;
    }
}

extern "C" void kernel_launch(void* const* d_in, const int* in_sizes, int n_in,
                              void* d_out, int out_size) {
    const float4* logits4 = (const float4*)d_in[0];
    const int*    labels  = (const int*)d_in[1];
    int nrows = in_sizes[1];               // labels element count == N rows

    // 3 CTAs/SM x 148 SMs = 444 blocks (proven best occupancy point)
    mce_main_kernel<<<444, 256>>>(logits4, labels, (float*)d_out, nrows);
}